// round 12
// baseline (speedup 1.0000x reference)
#include <cuda_runtime.h>
#include <cstdint>
#include <math.h>

// Symmetric Hausdorff distance, B=4, N=M=8192, D=3, fp32 — threshold-pruned.
//
// k_prep:   convert pred/gt to float4 arrays (vector loads everywhere after),
//           init per-row seed mins to +INF.
// k_seed:   exact mins for 256 strided rows per (dir,batch). Warp = 4 rows x
//           2048-target slice (target load amortized over 4 queries, short
//           chains, 2048 warps). Partials -> atomicMin g_seedmin (int bits of
//           d^2 >= 0: exact, order-free).
// k_thresh: g_res[b] = max over both directions' 256 seeded row mins.
// k_main:   all other rows; warp = row, lanes over targets; every 128 targets
//           warp REDUX min vs g_res[b] (uniform break). The argmax row's
//           partial min is always >= answer >= threshold, so it is never
//           pruned -> exact, bitwise-deterministic output.
// k_fin:    out[b] = sqrt(g_res[b]).

#define BATCH 4
#define NPB 8192
#define TOT (2*BATCH*NPB)        // 65536 points
#define SEEDROWS 256             // per (dir,batch); rows n = 32*k
#define FINF_BITS 0x7f800000

__device__ float4 g_pts4[TOT];           // [set][batch][n] : set 0=pred, 1=gt
__device__ int    g_seedmin[8*SEEDROWS]; // per (dir*4+b, k) exact row min bits
__device__ int    g_res[BATCH];          // per-batch threshold / final max

__device__ __forceinline__ float dist2(const float4 q, const float4 t) {
    float dx = q.x - t.x, dy = q.y - t.y, dz = q.z - t.z;
    return fmaf(dx, dx, fmaf(dy, dy, dz * dz));
}

__global__ void k_prep(const float* __restrict__ pred,
                       const float* __restrict__ gt) {
    int i = blockIdx.x * blockDim.x + threadIdx.x;
    if (i < 8 * SEEDROWS) g_seedmin[i] = FINF_BITS;
    if (i >= TOT) return;
    const float* s = (i < BATCH * NPB) ? (pred + 3 * (size_t)i)
                                       : (gt + 3 * (size_t)(i - BATCH * NPB));
    g_pts4[i] = make_float4(s[0], s[1], s[2], 0.0f);
}

// 2048 warps: (db: 8) x (rowgroup: 64) x (target-slice: 4).
__global__ __launch_bounds__(256) void k_seed() {
    const int warp = threadIdx.x >> 5, lane = threadIdx.x & 31;
    const int gw = blockIdx.x * 8 + warp;          // 0..2047
    const int ts = gw & 3;                         // target slice (2048 each)
    const int rg = (gw >> 2) & 63;                 // row group (4 rows)
    const int db = gw >> 8;                        // dir*4 + b
    const int dir = db >> 2, b = db & 3;

    const float4* __restrict__ Q = g_pts4 + (size_t)dir * BATCH * NPB + (size_t)b * NPB;
    const float4* __restrict__ T = g_pts4 + (size_t)(1 - dir) * BATCH * NPB + (size_t)b * NPB;

    float4 q0 = Q[(rg * 4 + 0) * 32];
    float4 q1 = Q[(rg * 4 + 1) * 32];
    float4 q2 = Q[(rg * 4 + 2) * 32];
    float4 q3 = Q[(rg * 4 + 3) * 32];
    float r0 = __int_as_float(FINF_BITS), r1 = r0, r2 = r0, r3 = r0;

    const int j0 = ts * 2048;
#pragma unroll 2
    for (int j = j0 + lane; j < j0 + 2048; j += 32) {
        const float4 t = T[j];                     // one LDG.128, 4 queries
        r0 = fminf(r0, dist2(q0, t));
        r1 = fminf(r1, dist2(q1, t));
        r2 = fminf(r2, dist2(q2, t));
        r3 = fminf(r3, dist2(q3, t));
    }
    unsigned m0 = __reduce_min_sync(0xffffffffu, (unsigned)__float_as_int(r0));
    unsigned m1 = __reduce_min_sync(0xffffffffu, (unsigned)__float_as_int(r1));
    unsigned m2 = __reduce_min_sync(0xffffffffu, (unsigned)__float_as_int(r2));
    unsigned m3 = __reduce_min_sync(0xffffffffu, (unsigned)__float_as_int(r3));
    if (lane == 0) {
        atomicMin(&g_seedmin[db * SEEDROWS + rg * 4 + 0], (int)m0);
        atomicMin(&g_seedmin[db * SEEDROWS + rg * 4 + 1], (int)m1);
        atomicMin(&g_seedmin[db * SEEDROWS + rg * 4 + 2], (int)m2);
        atomicMin(&g_seedmin[db * SEEDROWS + rg * 4 + 3], (int)m3);
    }
}

__global__ void k_thresh() {
    __shared__ int red[256];
    const int b = blockIdx.x, tid = threadIdx.x;
    int v = 0;
    // both directions of batch b: db = b and b + 4
    v = max(v, g_seedmin[b * SEEDROWS + tid]);
    v = max(v, g_seedmin[(b + 4) * SEEDROWS + tid]);
    red[tid] = v; __syncthreads();
    for (int s = 128; s > 0; s >>= 1) {
        if (tid < s) red[tid] = max(red[tid], red[tid + s]);
        __syncthreads();
    }
    if (tid == 0) g_res[b] = red[0];               // plain store (pre-main)
}

// 65536 warps: warp = one unseeded row.
__global__ __launch_bounds__(512) void k_main() {
    const int warp = threadIdx.x >> 5, lane = threadIdx.x & 31;
    const int db = blockIdx.x >> 9;                // 0..7
    const int n  = (blockIdx.x & 511) * 16 + warp; // 0..8191
    if ((n & 31) == 0) return;                     // covered by k_seed
    const int dir = db >> 2, b = db & 3;

    const float4* __restrict__ Q = g_pts4 + (size_t)dir * BATCH * NPB + (size_t)b * NPB;
    const float4* __restrict__ T = g_pts4 + (size_t)(1 - dir) * BATCH * NPB + (size_t)b * NPB;

    const float4 q = Q[n];
    float rmin = __int_as_float(FINF_BITS);
    unsigned wm = FINF_BITS;
    for (int j0 = 0; j0 < NPB; j0 += 128) {
#pragma unroll
        for (int s = 0; s < 4; s++)
            rmin = fminf(rmin, dist2(q, T[j0 + s * 32 + lane]));  // LDG.128
        wm = __reduce_min_sync(0xffffffffu, (unsigned)__float_as_int(rmin));
        int thr = __ldcg(&g_res[b]);               // stale read only under-prunes
        if (__int_as_float((int)wm) < __int_as_float(thr)) return;  // uniform
    }
    if (lane == 0) atomicMax(&g_res[b], (int)wm);  // exact completed row min
}

__global__ void k_fin(float* __restrict__ out) {
    const int b = threadIdx.x;
    if (b < BATCH) out[b] = sqrtf(__int_as_float(g_res[b]));
}

extern "C" void kernel_launch(void* const* d_in, const int* in_sizes, int n_in,
                              void* d_out, int out_size) {
    const float* pred = (const float*)d_in[0];
    const float* gt   = (const float*)d_in[1];
    float* out = (float*)d_out;

    k_prep<<<TOT / 256, 256>>>(pred, gt);
    k_seed<<<256, 256>>>();
    k_thresh<<<BATCH, 256>>>();
    k_main<<<4096, 512>>>();
    k_fin<<<1, 32>>>(out);
}